// round 16
// baseline (speedup 1.0000x reference)
#include <cuda_runtime.h>
#include <cuda_fp16.h>
#include <mma.h>
#include <math.h>
using namespace nvcuda;

#define N_NODES 50000
#define N_PAD   50016     // multiple of 32
#define E_MAX   800000
#define SCAN_BLOCKS 196   // 196*256 = 50176 >= 50000

// split points for ea0 / nl1 pipelining
#define SPLIT_NODES 25024           // = 782 * 32
#define NL_BLK0     782             // nl1 part0 blocks
#define NL_BLK1     (N_PAD / 32 - NL_BLK0)
#define EA_BLK0     (SPLIT_NODES / 4)                 // 6256
#define EA_BLK1     ((N_NODES - SPLIT_NODES + 3) / 4) // 6244

// div_term[i] = 10^(-i/4) = exp(-i*ln(10000)/16), i = 0..15 (exact table)
__constant__ float c_dv[16] = {
    1.0f, 0.5623413251903491f, 0.31622776601683794f, 0.17782794100389228f,
    0.1f, 0.05623413251903491f, 0.031622776601683794f, 0.017782794100389228f,
    0.01f, 0.005623413251903491f, 0.0031622776601683794f, 0.0017782794100389228f,
    0.001f, 0.0005623413251903491f, 0.00031622776601683794f, 0.00017782794100389228f};

// ---------------- static device scratch (zero-initialized, incl. pad rows) ----------------
// DOUBLE-BUFFERED per layer: edge_agg<L> gathers from ALL nodes' k/v/q of layer L,
// so layer-2 node_linear must never overwrite layer-1 buffers while ea0 still runs.
__device__ float  g_q0 [N_PAD * 128];
__device__ float  g_q1 [N_PAD * 128];
__device__ __half g_kh0[N_PAD * 128];
__device__ __half g_kh1[N_PAD * 128];
__device__ __half g_vh0[N_PAD * 128];
__device__ __half g_vh1[N_PAD * 128];
__device__ float  g_qt0[N_PAD * 128];
__device__ float  g_qt1[N_PAD * 128];
__device__ float  g_qbt0[N_PAD * 4];
__device__ float  g_qbt1[N_PAD * 4];
__device__ __half g_xh [N_PAD * 64];    // emb -> half
__device__ __half g_x1h[N_PAD * 128];   // layer-1 output (half), pad rows stay 0
__device__ float  g_xc [N_NODES];
__device__ __half g_w1 [3 * 64 * 128];  // wq1|wk1|wv1 as half
__device__ __half g_wt1[32 * 128];
__device__ __half g_w2 [3 * 128 * 128];
__device__ __half g_wt2[32 * 128];
__device__ int    g_deg[N_NODES];
__device__ int    g_cur[N_NODES];
__device__ int    g_off[N_NODES + 1];
__device__ int    g_bsum[SCAN_BLOCKS];
__device__ int    g_bpre[SCAN_BLOCKS];
__device__ unsigned long long g_se[E_MAX];  // {src, t-bits} sorted by dst

// ---------------- merged setup: conversions + histogram ----------------
__global__ void setup_kernel(const float* __restrict__ emb,
                             const float* __restrict__ wq1, const float* __restrict__ wk1,
                             const float* __restrict__ wv1, const float* __restrict__ wt1,
                             const float* __restrict__ wq2, const float* __restrict__ wk2,
                             const float* __restrict__ wv2, const float* __restrict__ wt2,
                             const int* __restrict__ ei, int E) {
    int i = blockIdx.x * 256 + threadIdx.x;
    if (i < N_NODES * 64) g_xh[i] = __float2half(emb[i]);
    if (i < E) atomicAdd(&g_deg[ei[E + i]], 1);     // histogram (g_deg pre-zeroed)
    {
        const int per = 64 * 128;
        if (i < 3 * per) {
            const float* s = (i < per) ? wq1 : ((i < 2 * per) ? wk1 : wv1);
            g_w1[i] = __float2half(s[i % per]);
        }
    }
    {
        const int per = 128 * 128;
        if (i < 3 * per) {
            const float* s = (i < per) ? wq2 : ((i < 2 * per) ? wk2 : wv2);
            g_w2[i] = __float2half(s[i % per]);
        }
    }
    if (i < 32 * 128) {
        g_wt1[i] = __float2half(wt1[i]);
        g_wt2[i] = __float2half(wt2[i]);
    }
}

// ---------------- counting sort scan chain ----------------
__global__ void scanA_kernel(int n) {
    __shared__ int sh[256];
    int t = threadIdx.x;
    int i = blockIdx.x * 256 + t;
    int v = (i < n) ? g_deg[i] : 0;
    sh[t] = v;
    __syncthreads();
    for (int o = 1; o < 256; o <<= 1) {
        int u = (t >= o) ? sh[t - o] : 0;
        __syncthreads();
        sh[t] += u;
        __syncthreads();
    }
    if (i < n) g_off[i] = sh[t] - v;
    if (t == 255) g_bsum[blockIdx.x] = sh[255];
}

__global__ void scanB_kernel(int nb, int n) {
    __shared__ int sh[256];
    int t = threadIdx.x;
    int v = (t < nb) ? g_bsum[t] : 0;
    sh[t] = v;
    __syncthreads();
    for (int o = 1; o < 256; o <<= 1) {
        int u = (t >= o) ? sh[t - o] : 0;
        __syncthreads();
        sh[t] += u;
        __syncthreads();
    }
    if (t < nb) g_bpre[t] = sh[t] - v;
    if (t == 255) g_off[n] = sh[255];
}

__global__ void scanC_kernel(int n) {
    int i = blockIdx.x * 256 + threadIdx.x;
    if (i < n) g_off[i] += g_bpre[blockIdx.x];
}

__global__ void scatter_kernel(const int* __restrict__ ei,
                               const float* __restrict__ ea, int E) {
    int e = blockIdx.x * blockDim.x + threadIdx.x;
    if (e >= E) return;
    int d = ei[E + e];
    int pos = g_off[d] + atomicAdd(&g_cur[d], 1);
    g_se[pos] = (unsigned int)ei[e] |
        ((unsigned long long)__float_as_uint(ea[2 * e + 1]) << 32);
}

// ---------------- tensor-core node linear: q, k(fp16), v(fp16), qt, qbt ----------------
// q path scaled by (1/sqrt(32)) * log2(e) so edge_agg can use exp2f directly.
template <int L>
__global__ __launch_bounds__(256) void node_linear_wmma(
    const float* __restrict__ bq, const float* __restrict__ bk,
    const float* __restrict__ bv, const float* __restrict__ bt, int blk_off)
{
    constexpr int D = (L == 0) ? 64 : 128;
    const __half* __restrict__ xh  = (L == 0) ? g_xh  : g_x1h;
    const __half* __restrict__ wh  = (L == 0) ? g_w1  : g_w2;
    const __half* __restrict__ wth = (L == 0) ? g_wt1 : g_wt2;
    float*  __restrict__ gq   = (L == 0) ? g_q0   : g_q1;
    __half* __restrict__ gkh  = (L == 0) ? g_kh0  : g_kh1;
    __half* __restrict__ gvh  = (L == 0) ? g_vh0  : g_vh1;
    float*  __restrict__ gqt  = (L == 0) ? g_qt0  : g_qt1;
    float*  __restrict__ gqbt = (L == 0) ? g_qbt0 : g_qbt1;

    __shared__ float  stage[32 * 128];   // 16 KB
    __shared__ __half qsh[32 * 128];     // 8 KB
    const int w = threadIdx.x >> 5;
    const int node0 = (blockIdx.x + blk_off) * 32;

    wmma::fragment<wmma::accumulator, 16, 16, 16, float> acc[3][2];
#pragma unroll
    for (int m = 0; m < 3; m++)
#pragma unroll
        for (int r = 0; r < 2; r++) wmma::fill_fragment(acc[m][r], 0.f);

#pragma unroll
    for (int k0 = 0; k0 < D; k0 += 16) {
        wmma::fragment<wmma::matrix_a, 16, 16, 16, __half, wmma::row_major> a0, a1;
        wmma::load_matrix_sync(a0, xh + (size_t)node0 * D + k0, D);
        wmma::load_matrix_sync(a1, xh + (size_t)(node0 + 16) * D + k0, D);
#pragma unroll
        for (int m = 0; m < 3; m++) {
            wmma::fragment<wmma::matrix_b, 16, 16, 16, __half, wmma::row_major> b;
            wmma::load_matrix_sync(b, wh + m * (D * 128) + k0 * 128 + w * 16, 128);
            wmma::mma_sync(acc[m][0], a0, b, acc[m][0]);
            wmma::mma_sync(acc[m][1], a1, b, acc[m][1]);
        }
    }

    // (1/sqrt(32)) * log2(e)
    const float inv = 0.25503482f;
#pragma unroll
    for (int m = 0; m < 3; m++) {
        wmma::store_matrix_sync(stage + w * 16, acc[m][0], 128, wmma::mem_row_major);
        wmma::store_matrix_sync(stage + 16 * 128 + w * 16, acc[m][1], 128, wmma::mem_row_major);
        __syncthreads();
        for (int i = threadIdx.x; i < 32 * 128; i += 256) {
            int c = i & 127;
            int node = node0 + (i >> 7);
            float val = stage[i];
            if (m == 0) {
                float qv = (val + bq[c]) * inv;
                qsh[i] = __float2half(qv);
                gq[(size_t)node * 128 + c] = qv;
            } else if (m == 1) {
                gkh[(size_t)node * 128 + c] = __float2half(val + bk[c]);
            } else {
                gvh[(size_t)node * 128 + c] = __float2half(val + bv[c]);
            }
        }
        __syncthreads();
    }

    // qt GEMM: per-head 32x32; warp w -> head h = w>>1, col offset d0 = (w&1)*16
    {
        int h = w >> 1, d0 = (w & 1) * 16;
        wmma::fragment<wmma::accumulator, 16, 16, 16, float> q0, q1;
        wmma::fill_fragment(q0, 0.f);
        wmma::fill_fragment(q1, 0.f);
#pragma unroll
        for (int k0 = 0; k0 < 32; k0 += 16) {
            wmma::fragment<wmma::matrix_a, 16, 16, 16, __half, wmma::row_major> a0, a1;
            wmma::fragment<wmma::matrix_b, 16, 16, 16, __half, wmma::col_major> b;
            wmma::load_matrix_sync(a0, qsh + h * 32 + k0, 128);
            wmma::load_matrix_sync(a1, qsh + 16 * 128 + h * 32 + k0, 128);
            wmma::load_matrix_sync(b, wth + h * 32 + k0 + d0 * 128, 128);
            wmma::mma_sync(q0, a0, b, q0);
            wmma::mma_sync(q1, a1, b, q1);
        }
        wmma::store_matrix_sync(gqt + (size_t)node0 * 128 + h * 32 + d0, q0, 128, wmma::mem_row_major);
        wmma::store_matrix_sync(gqt + (size_t)(node0 + 16) * 128 + h * 32 + d0, q1, 128, wmma::mem_row_major);
    }

    // qbt: node n, head hh -> dot(q'[n, hh*32:+32], bt[hh*32:+32])
    if (threadIdx.x < 128) {
        int n = threadIdx.x >> 2, hh = threadIdx.x & 3;
        float b = 0.f;
#pragma unroll
        for (int c = 0; c < 32; c++)
            b = fmaf(__half2float(qsh[n * 128 + hh * 32 + c]), bt[hh * 32 + c], b);
        gqbt[(size_t)(node0 + n) * 4 + hh] = b;
    }
}

// ---------------- per-node softmax aggregation ----------------
// Mapping (R13): warp = node; half = lane>>4 picks one of 2 edges per iter;
// sl = lane&15 owns output dims [sl*8, sl*8+8). exp2f (log2e folded into q path).
template <int LAYER>
__global__ __launch_bounds__(128) void edge_agg_kernel(const float* __restrict__ wc,
                                                       int node_off, int node_hi) {
    const float*  __restrict__ gq   = (LAYER == 0) ? g_q0   : g_q1;
    const __half* __restrict__ gkh  = (LAYER == 0) ? g_kh0  : g_kh1;
    const __half* __restrict__ gvh  = (LAYER == 0) ? g_vh0  : g_vh1;
    const float*  __restrict__ gqt  = (LAYER == 0) ? g_qt0  : g_qt1;
    const float*  __restrict__ gqbt = (LAYER == 0) ? g_qbt0 : g_qbt1;

    const int lane = threadIdx.x & 31;
    const int node = node_off + blockIdx.x * 4 + (threadIdx.x >> 5);
    if (node >= node_hi) return;

    const int sl   = lane & 15;
    const int half = lane >> 4;
    const int D0   = sl * 8;        // output dims owned
    const int h    = sl >> 2;       // head
    const int m    = sl & 3;        // slice within head

    const int start = g_off[node], end = g_off[node + 1];
    if (start >= end) {
        if (LAYER == 0) {
            if (half == 0)
                *reinterpret_cast<uint4*>(g_x1h + (size_t)node * 128 + D0) =
                    make_uint4(0u, 0u, 0u, 0u);
        } else if (lane == 0) {
            g_xc[node] = 0.f;
        }
        return;
    }

    const float4* qp  = reinterpret_cast<const float4*>(gq  + (size_t)node * 128 + D0);
    const float4* qtp = reinterpret_cast<const float4*>(gqt + (size_t)node * 128 + D0);
    float4 qa = qp[0],  qb = qp[1];
    float4 ta = qtp[0], tb = qtp[1];
    const float qbt = gqbt[(size_t)node * 4 + h];

    const float dv0 = c_dv[m * 4 + 0];
    const float dv1 = c_dv[m * 4 + 1];
    const float dv2 = c_dv[m * 4 + 2];
    const float dv3 = c_dv[m * 4 + 3];

    float a0 = 0.f, a1 = 0.f, a2 = 0.f, a3 = 0.f;
    float a4 = 0.f, a5 = 0.f, a6 = 0.f, a7 = 0.f;
    float s = 0.f;

#pragma unroll 2
    for (int base = start; base < end; base += 2) {
        int e = base + half;
        bool valid = e < end;
        int ce = valid ? e : end - 1;
        unsigned long long se = g_se[ce];
        int   src = (int)(unsigned int)se;
        float tv  = __uint_as_float((unsigned int)(se >> 32));

        uint4 kk = *reinterpret_cast<const uint4*>(gkh + (size_t)src * 128 + D0);
        uint4 vv = *reinterpret_cast<const uint4*>(gvh + (size_t)src * 128 + D0);

        float2 k0 = __half22float2(*reinterpret_cast<__half2*>(&kk.x));
        float2 k1 = __half22float2(*reinterpret_cast<__half2*>(&kk.y));
        float2 k2 = __half22float2(*reinterpret_cast<__half2*>(&kk.z));
        float2 k3 = __half22float2(*reinterpret_cast<__half2*>(&kk.w));

        float p = qa.x * k0.x;
        p = fmaf(qa.y, k0.y, p); p = fmaf(qa.z, k1.x, p); p = fmaf(qa.w, k1.y, p);
        p = fmaf(qb.x, k2.x, p); p = fmaf(qb.y, k2.y, p);
        p = fmaf(qb.z, k3.x, p); p = fmaf(qb.w, k3.y, p);

        float g0 = tv * dv0, g1 = tv * dv1, g2 = tv * dv2, g3 = tv * dv3;
        p = fmaf(ta.x, __sinf(g0), p); p = fmaf(ta.y, __cosf(g0), p);
        p = fmaf(ta.z, __sinf(g1), p); p = fmaf(ta.w, __cosf(g1), p);
        p = fmaf(tb.x, __sinf(g2), p); p = fmaf(tb.y, __cosf(g2), p);
        p = fmaf(tb.z, __sinf(g3), p); p = fmaf(tb.w, __cosf(g3), p);

        p += __shfl_xor_sync(0xffffffffu, p, 1);
        p += __shfl_xor_sync(0xffffffffu, p, 2);
        float alpha = p + qbt;                       // log2 domain
        float pe = valid ? exp2f(fminf(alpha, 100.f)) : 0.f;

        float2 v0 = __half22float2(*reinterpret_cast<__half2*>(&vv.x));
        float2 v1 = __half22float2(*reinterpret_cast<__half2*>(&vv.y));
        float2 v2 = __half22float2(*reinterpret_cast<__half2*>(&vv.z));
        float2 v3 = __half22float2(*reinterpret_cast<__half2*>(&vv.w));

        s += pe;
        a0 = fmaf(pe, v0.x, a0); a1 = fmaf(pe, v0.y, a1);
        a2 = fmaf(pe, v1.x, a2); a3 = fmaf(pe, v1.y, a3);
        a4 = fmaf(pe, v2.x, a4); a5 = fmaf(pe, v2.y, a5);
        a6 = fmaf(pe, v3.x, a6); a7 = fmaf(pe, v3.y, a7);
    }

    s  += __shfl_xor_sync(0xffffffffu, s,  16);
    a0 += __shfl_xor_sync(0xffffffffu, a0, 16);
    a1 += __shfl_xor_sync(0xffffffffu, a1, 16);
    a2 += __shfl_xor_sync(0xffffffffu, a2, 16);
    a3 += __shfl_xor_sync(0xffffffffu, a3, 16);
    a4 += __shfl_xor_sync(0xffffffffu, a4, 16);
    a5 += __shfl_xor_sync(0xffffffffu, a5, 16);
    a6 += __shfl_xor_sync(0xffffffffu, a6, 16);
    a7 += __shfl_xor_sync(0xffffffffu, a7, 16);

    float r = 1.f / (s + 1e-37f);
    float o0 = fmaxf(a0 * r, 0.f), o1 = fmaxf(a1 * r, 0.f);
    float o2 = fmaxf(a2 * r, 0.f), o3 = fmaxf(a3 * r, 0.f);
    float o4 = fmaxf(a4 * r, 0.f), o5 = fmaxf(a5 * r, 0.f);
    float o6 = fmaxf(a6 * r, 0.f), o7 = fmaxf(a7 * r, 0.f);

    if (LAYER == 0) {
        if (half == 0) {
            __half2 h0 = __floats2half2_rn(o0, o1);
            __half2 h1 = __floats2half2_rn(o2, o3);
            __half2 h2 = __floats2half2_rn(o4, o5);
            __half2 h3 = __floats2half2_rn(o6, o7);
            uint4 u;
            u.x = *reinterpret_cast<unsigned*>(&h0);
            u.y = *reinterpret_cast<unsigned*>(&h1);
            u.z = *reinterpret_cast<unsigned*>(&h2);
            u.w = *reinterpret_cast<unsigned*>(&h3);
            *reinterpret_cast<uint4*>(g_x1h + (size_t)node * 128 + D0) = u;
        }
    } else {
        const float4* wp = reinterpret_cast<const float4*>(wc + D0);
        float4 wa = wp[0], wb = wp[1];
        float p = o0 * wa.x;
        p = fmaf(o1, wa.y, p); p = fmaf(o2, wa.z, p); p = fmaf(o3, wa.w, p);
        p = fmaf(o4, wb.x, p); p = fmaf(o5, wb.y, p);
        p = fmaf(o6, wb.z, p); p = fmaf(o7, wb.w, p);
        p += __shfl_xor_sync(0xffffffffu, p, 1);
        p += __shfl_xor_sync(0xffffffffu, p, 2);
        p += __shfl_xor_sync(0xffffffffu, p, 4);
        p += __shfl_xor_sync(0xffffffffu, p, 8);
        if (lane == 0) g_xc[node] = p;
    }
}

// ---------------- final: out[e] = xc[src] + xc[dst] + bc ; re-zero counters ----------------
__global__ void final_kernel(const int* __restrict__ ei, const float* __restrict__ bc,
                             float* __restrict__ out, int E) {
    int e = blockIdx.x * blockDim.x + threadIdx.x;
    if (e < N_NODES) { g_deg[e] = 0; g_cur[e] = 0; }   // ready for next replay
    if (e >= E) return;
    out[e] = g_xc[ei[e]] + g_xc[ei[E + e]] + bc[0];
}

// ---------------- launch (capture fork/join; ea0/nl1 pipelined, race-free) ----------------
extern "C" void kernel_launch(void* const* d_in, const int* in_sizes, int n_in,
                              void* d_out, int out_size) {
    const int*   ei  = (const int*)  d_in[0];
    const float* ea  = (const float*)d_in[1];
    const float* emb = (const float*)d_in[3];
    const float *wq1 = (const float*)d_in[4],  *bq1 = (const float*)d_in[5];
    const float *wk1 = (const float*)d_in[6],  *bk1 = (const float*)d_in[7];
    const float *wv1 = (const float*)d_in[8],  *bv1 = (const float*)d_in[9];
    const float *wt1 = (const float*)d_in[10], *bt1 = (const float*)d_in[11];
    const float *wq2 = (const float*)d_in[12], *bq2 = (const float*)d_in[13];
    const float *wk2 = (const float*)d_in[14], *bk2 = (const float*)d_in[15];
    const float *wv2 = (const float*)d_in[16], *bv2 = (const float*)d_in[17];
    const float *wt2 = (const float*)d_in[18], *bt2 = (const float*)d_in[19];
    const float *wc  = (const float*)d_in[20], *bc  = (const float*)d_in[21];
    float* out = (float*)d_out;

    int E = in_sizes[0] / 2;

    // Fresh side stream + events each call (deterministic; host-side objects,
    // intentionally leaked — kernel_launch runs only a handful of times).
    cudaStream_t s2;
    cudaStreamCreateWithFlags(&s2, cudaStreamNonBlocking);
    cudaEvent_t ev1, ev2, ev3, ev4;
    cudaEventCreateWithFlags(&ev1, cudaEventDisableTiming);
    cudaEventCreateWithFlags(&ev2, cudaEventDisableTiming);
    cudaEventCreateWithFlags(&ev3, cudaEventDisableTiming);
    cudaEventCreateWithFlags(&ev4, cudaEventDisableTiming);

    // setup: conversions + histogram (g_deg zeroed by previous call's final_kernel)
    setup_kernel<<<(N_NODES * 64 + 255) / 256, 256>>>(emb, wq1, wk1, wv1, wt1,
                                                      wq2, wk2, wv2, wt2, ei, E);
    cudaEventRecord(ev1, 0);
    cudaStreamWaitEvent(s2, ev1, 0);

    // fork: sort chain on s2, node_linear<0> on main (independent)
    scanA_kernel<<<SCAN_BLOCKS, 256, 0, s2>>>(N_NODES);
    scanB_kernel<<<1, 256, 0, s2>>>(SCAN_BLOCKS, N_NODES);
    scanC_kernel<<<SCAN_BLOCKS, 256, 0, s2>>>(N_NODES);
    scatter_kernel<<<(E + 255) / 256, 256, 0, s2>>>(ei, ea, E);
    cudaEventRecord(ev2, s2);

    node_linear_wmma<0><<<N_PAD / 32, 256>>>(bq1, bk1, bv1, bt1, 0);

    // join, then pipelined ea0 / nl1 (nl1 writes LAYER-1-DISJOINT buffers):
    cudaStreamWaitEvent(0, ev2, 0);
    edge_agg_kernel<0><<<EA_BLK0, 128>>>(wc, 0, SPLIT_NODES);              // ea0 p0 (main)
    cudaEventRecord(ev3, 0);
    cudaStreamWaitEvent(s2, ev3, 0);
    node_linear_wmma<1><<<NL_BLK0, 256, 0, s2>>>(bq2, bk2, bv2, bt2, 0);   // nl1 p0 (s2)
    cudaEventRecord(ev4, s2);

    edge_agg_kernel<0><<<EA_BLK1, 128>>>(wc, SPLIT_NODES, N_NODES);        // ea0 p1 (main)
    node_linear_wmma<1><<<NL_BLK1, 256>>>(bq2, bk2, bv2, bt2, NL_BLK0);    // nl1 p1 (main)

    cudaStreamWaitEvent(0, ev4, 0);
    edge_agg_kernel<1><<<(N_NODES + 3) / 4, 128>>>(wc, 0, N_NODES);

    final_kernel<<<(E + 255) / 256, 256>>>(ei, bc, out, E);
}

// round 17
// speedup vs baseline: 1.0363x; 1.0363x over previous
#include <cuda_runtime.h>
#include <cuda_fp16.h>
#include <mma.h>
#include <math.h>
using namespace nvcuda;

#define N_NODES 50000
#define N_PAD   50016     // multiple of 32
#define E_MAX   800000
#define SCAN_BLOCKS 196   // 196*256 = 50176 >= 50000

// div_term[i] = 10^(-i/4) = exp(-i*ln(10000)/16), i = 0..15 (exact table)
__constant__ float c_dv[16] = {
    1.0f, 0.5623413251903491f, 0.31622776601683794f, 0.17782794100389228f,
    0.1f, 0.05623413251903491f, 0.031622776601683794f, 0.017782794100389228f,
    0.01f, 0.005623413251903491f, 0.0031622776601683794f, 0.0017782794100389228f,
    0.001f, 0.0005623413251903491f, 0.00031622776601683794f, 0.00017782794100389228f};

// ---------------- static device scratch (zero-initialized, incl. pad rows) ----------------
// g_deg / g_cur zero at first call (static init) and re-zeroed by final_kernel
// at the end of EVERY call -> every graph replay sees zeros. Deterministic.
__device__ float  g_q  [N_PAD * 128];
__device__ __half g_kh [N_PAD * 128];
__device__ __half g_vh [N_PAD * 128];
__device__ float  g_qt [N_PAD * 128];
__device__ float  g_qbt[N_PAD * 4];
__device__ __half g_xh [N_PAD * 64];    // emb -> half
__device__ __half g_x1h[N_PAD * 128];   // layer-1 output (half), pad rows stay 0
__device__ float  g_xc [N_NODES];
__device__ __half g_w1 [3 * 64 * 128];  // wq1|wk1|wv1 as half
__device__ __half g_wt1[32 * 128];
__device__ __half g_w2 [3 * 128 * 128];
__device__ __half g_wt2[32 * 128];
__device__ int    g_deg[N_NODES];
__device__ int    g_cur[N_NODES];
__device__ int    g_off[N_NODES + 1];
__device__ int    g_bsum[SCAN_BLOCKS];
__device__ int    g_bpre[SCAN_BLOCKS];
__device__ unsigned long long g_se[E_MAX];  // {src, t-bits} sorted by dst

// ---------------- merged setup: conversions + histogram ----------------
__global__ void setup_kernel(const float* __restrict__ emb,
                             const float* __restrict__ wq1, const float* __restrict__ wk1,
                             const float* __restrict__ wv1, const float* __restrict__ wt1,
                             const float* __restrict__ wq2, const float* __restrict__ wk2,
                             const float* __restrict__ wv2, const float* __restrict__ wt2,
                             const int* __restrict__ ei, int E) {
    int i = blockIdx.x * 256 + threadIdx.x;
    if (i < N_NODES * 64) g_xh[i] = __float2half(emb[i]);
    if (i < E) atomicAdd(&g_deg[ei[E + i]], 1);     // histogram (g_deg pre-zeroed)
    {
        const int per = 64 * 128;
        if (i < 3 * per) {
            const float* s = (i < per) ? wq1 : ((i < 2 * per) ? wk1 : wv1);
            g_w1[i] = __float2half(s[i % per]);
        }
    }
    {
        const int per = 128 * 128;
        if (i < 3 * per) {
            const float* s = (i < per) ? wq2 : ((i < 2 * per) ? wk2 : wv2);
            g_w2[i] = __float2half(s[i % per]);
        }
    }
    if (i < 32 * 128) {
        g_wt1[i] = __float2half(wt1[i]);
        g_wt2[i] = __float2half(wt2[i]);
    }
}

// ---------------- counting sort scan chain ----------------
__global__ void scanA_kernel(int n) {
    __shared__ int sh[256];
    int t = threadIdx.x;
    int i = blockIdx.x * 256 + t;
    int v = (i < n) ? g_deg[i] : 0;
    sh[t] = v;
    __syncthreads();
    for (int o = 1; o < 256; o <<= 1) {
        int u = (t >= o) ? sh[t - o] : 0;
        __syncthreads();
        sh[t] += u;
        __syncthreads();
    }
    if (i < n) g_off[i] = sh[t] - v;
    if (t == 255) g_bsum[blockIdx.x] = sh[255];
}

__global__ void scanB_kernel(int nb, int n) {
    __shared__ int sh[256];
    int t = threadIdx.x;
    int v = (t < nb) ? g_bsum[t] : 0;
    sh[t] = v;
    __syncthreads();
    for (int o = 1; o < 256; o <<= 1) {
        int u = (t >= o) ? sh[t - o] : 0;
        __syncthreads();
        sh[t] += u;
        __syncthreads();
    }
    if (t < nb) g_bpre[t] = sh[t] - v;
    if (t == 255) g_off[n] = sh[255];
}

__global__ void scanC_kernel(int n) {
    int i = blockIdx.x * 256 + threadIdx.x;
    if (i < n) g_off[i] += g_bpre[blockIdx.x];
}

__global__ void scatter_kernel(const int* __restrict__ ei,
                               const float* __restrict__ ea, int E) {
    int e = blockIdx.x * blockDim.x + threadIdx.x;
    if (e >= E) return;
    int d = ei[E + e];
    int pos = g_off[d] + atomicAdd(&g_cur[d], 1);
    g_se[pos] = (unsigned int)ei[e] |
        ((unsigned long long)__float_as_uint(ea[2 * e + 1]) << 32);
}

// ---------------- tensor-core node linear: q, k(fp16), v(fp16), qt, qbt ----------------
// q path scaled by (1/sqrt(32)) * log2(e) so edge_agg can use exp2f directly;
// qt and qbt derive from the scaled q, inheriting the factor consistently.
template <int L>
__global__ __launch_bounds__(256) void node_linear_wmma(
    const float* __restrict__ bq, const float* __restrict__ bk,
    const float* __restrict__ bv, const float* __restrict__ bt)
{
    constexpr int D = (L == 0) ? 64 : 128;
    const __half* __restrict__ xh  = (L == 0) ? g_xh  : g_x1h;
    const __half* __restrict__ wh  = (L == 0) ? g_w1  : g_w2;
    const __half* __restrict__ wth = (L == 0) ? g_wt1 : g_wt2;

    __shared__ float  stage[32 * 128];   // 16 KB
    __shared__ __half qsh[32 * 128];     // 8 KB
    const int w = threadIdx.x >> 5;
    const int node0 = blockIdx.x * 32;

    wmma::fragment<wmma::accumulator, 16, 16, 16, float> acc[3][2];
#pragma unroll
    for (int m = 0; m < 3; m++)
#pragma unroll
        for (int r = 0; r < 2; r++) wmma::fill_fragment(acc[m][r], 0.f);

#pragma unroll
    for (int k0 = 0; k0 < D; k0 += 16) {
        wmma::fragment<wmma::matrix_a, 16, 16, 16, __half, wmma::row_major> a0, a1;
        wmma::load_matrix_sync(a0, xh + (size_t)node0 * D + k0, D);
        wmma::load_matrix_sync(a1, xh + (size_t)(node0 + 16) * D + k0, D);
#pragma unroll
        for (int m = 0; m < 3; m++) {
            wmma::fragment<wmma::matrix_b, 16, 16, 16, __half, wmma::row_major> b;
            wmma::load_matrix_sync(b, wh + m * (D * 128) + k0 * 128 + w * 16, 128);
            wmma::mma_sync(acc[m][0], a0, b, acc[m][0]);
            wmma::mma_sync(acc[m][1], a1, b, acc[m][1]);
        }
    }

    // (1/sqrt(32)) * log2(e)
    const float inv = 0.25503482f;
#pragma unroll
    for (int m = 0; m < 3; m++) {
        wmma::store_matrix_sync(stage + w * 16, acc[m][0], 128, wmma::mem_row_major);
        wmma::store_matrix_sync(stage + 16 * 128 + w * 16, acc[m][1], 128, wmma::mem_row_major);
        __syncthreads();
        for (int i = threadIdx.x; i < 32 * 128; i += 256) {
            int c = i & 127;
            int node = node0 + (i >> 7);
            float val = stage[i];
            if (m == 0) {
                float qv = (val + bq[c]) * inv;
                qsh[i] = __float2half(qv);
                g_q[(size_t)node * 128 + c] = qv;
            } else if (m == 1) {
                g_kh[(size_t)node * 128 + c] = __float2half(val + bk[c]);
            } else {
                g_vh[(size_t)node * 128 + c] = __float2half(val + bv[c]);
            }
        }
        __syncthreads();
    }

    // qt GEMM: per-head 32x32; warp w -> head h = w>>1, col offset d0 = (w&1)*16
    {
        int h = w >> 1, d0 = (w & 1) * 16;
        wmma::fragment<wmma::accumulator, 16, 16, 16, float> q0, q1;
        wmma::fill_fragment(q0, 0.f);
        wmma::fill_fragment(q1, 0.f);
#pragma unroll
        for (int k0 = 0; k0 < 32; k0 += 16) {
            wmma::fragment<wmma::matrix_a, 16, 16, 16, __half, wmma::row_major> a0, a1;
            wmma::fragment<wmma::matrix_b, 16, 16, 16, __half, wmma::col_major> b;
            wmma::load_matrix_sync(a0, qsh + h * 32 + k0, 128);
            wmma::load_matrix_sync(a1, qsh + 16 * 128 + h * 32 + k0, 128);
            wmma::load_matrix_sync(b, wth + h * 32 + k0 + d0 * 128, 128);
            wmma::mma_sync(q0, a0, b, q0);
            wmma::mma_sync(q1, a1, b, q1);
        }
        wmma::store_matrix_sync(g_qt + (size_t)node0 * 128 + h * 32 + d0, q0, 128, wmma::mem_row_major);
        wmma::store_matrix_sync(g_qt + (size_t)(node0 + 16) * 128 + h * 32 + d0, q1, 128, wmma::mem_row_major);
    }

    // qbt: node n, head hh -> dot(q'[n, hh*32:+32], bt[hh*32:+32])
    if (threadIdx.x < 128) {
        int n = threadIdx.x >> 2, hh = threadIdx.x & 3;
        float b = 0.f;
#pragma unroll
        for (int c = 0; c < 32; c++)
            b = fmaf(__half2float(qsh[n * 128 + hh * 32 + c]), bt[hh * 32 + c], b);
        g_qbt[(size_t)(node0 + n) * 4 + hh] = b;
    }
}

// ---------------- per-node softmax aggregation ----------------
// Mapping (R13): warp = node; half = lane>>4 picks one of 2 edges per iter;
// sl = lane&15 owns output dims [sl*8, sl*8+8). exp2f (log2e folded into q path).
template <int LAYER>
__global__ __launch_bounds__(128) void edge_agg_kernel(const float* __restrict__ wc) {
    const int lane = threadIdx.x & 31;
    const int node = blockIdx.x * 4 + (threadIdx.x >> 5);
    if (node >= N_NODES) return;

    const int sl   = lane & 15;
    const int half = lane >> 4;
    const int D0   = sl * 8;        // output dims owned
    const int h    = sl >> 2;       // head
    const int m    = sl & 3;        // slice within head

    const int start = g_off[node], end = g_off[node + 1];
    if (start >= end) {
        if (LAYER == 0) {
            if (half == 0)
                *reinterpret_cast<uint4*>(g_x1h + (size_t)node * 128 + D0) =
                    make_uint4(0u, 0u, 0u, 0u);
        } else if (lane == 0) {
            g_xc[node] = 0.f;
        }
        return;
    }

    const float4* qp  = reinterpret_cast<const float4*>(g_q  + (size_t)node * 128 + D0);
    const float4* qtp = reinterpret_cast<const float4*>(g_qt + (size_t)node * 128 + D0);
    float4 qa = qp[0],  qb = qp[1];
    float4 ta = qtp[0], tb = qtp[1];
    const float qbt = g_qbt[(size_t)node * 4 + h];

    const float dv0 = c_dv[m * 4 + 0];
    const float dv1 = c_dv[m * 4 + 1];
    const float dv2 = c_dv[m * 4 + 2];
    const float dv3 = c_dv[m * 4 + 3];

    float a0 = 0.f, a1 = 0.f, a2 = 0.f, a3 = 0.f;
    float a4 = 0.f, a5 = 0.f, a6 = 0.f, a7 = 0.f;
    float s = 0.f;

#pragma unroll 2
    for (int base = start; base < end; base += 2) {
        int e = base + half;
        bool valid = e < end;
        int ce = valid ? e : end - 1;
        unsigned long long se = g_se[ce];
        int   src = (int)(unsigned int)se;
        float tv  = __uint_as_float((unsigned int)(se >> 32));

        uint4 kk = *reinterpret_cast<const uint4*>(g_kh + (size_t)src * 128 + D0);
        uint4 vv = *reinterpret_cast<const uint4*>(g_vh + (size_t)src * 128 + D0);

        float2 k0 = __half22float2(*reinterpret_cast<__half2*>(&kk.x));
        float2 k1 = __half22float2(*reinterpret_cast<__half2*>(&kk.y));
        float2 k2 = __half22float2(*reinterpret_cast<__half2*>(&kk.z));
        float2 k3 = __half22float2(*reinterpret_cast<__half2*>(&kk.w));

        float p = qa.x * k0.x;
        p = fmaf(qa.y, k0.y, p); p = fmaf(qa.z, k1.x, p); p = fmaf(qa.w, k1.y, p);
        p = fmaf(qb.x, k2.x, p); p = fmaf(qb.y, k2.y, p);
        p = fmaf(qb.z, k3.x, p); p = fmaf(qb.w, k3.y, p);

        float g0 = tv * dv0, g1 = tv * dv1, g2 = tv * dv2, g3 = tv * dv3;
        p = fmaf(ta.x, __sinf(g0), p); p = fmaf(ta.y, __cosf(g0), p);
        p = fmaf(ta.z, __sinf(g1), p); p = fmaf(ta.w, __cosf(g1), p);
        p = fmaf(tb.x, __sinf(g2), p); p = fmaf(tb.y, __cosf(g2), p);
        p = fmaf(tb.z, __sinf(g3), p); p = fmaf(tb.w, __cosf(g3), p);

        p += __shfl_xor_sync(0xffffffffu, p, 1);
        p += __shfl_xor_sync(0xffffffffu, p, 2);
        float alpha = p + qbt;                       // log2 domain
        float pe = valid ? exp2f(fminf(alpha, 100.f)) : 0.f;

        float2 v0 = __half22float2(*reinterpret_cast<__half2*>(&vv.x));
        float2 v1 = __half22float2(*reinterpret_cast<__half2*>(&vv.y));
        float2 v2 = __half22float2(*reinterpret_cast<__half2*>(&vv.z));
        float2 v3 = __half22float2(*reinterpret_cast<__half2*>(&vv.w));

        s += pe;
        a0 = fmaf(pe, v0.x, a0); a1 = fmaf(pe, v0.y, a1);
        a2 = fmaf(pe, v1.x, a2); a3 = fmaf(pe, v1.y, a3);
        a4 = fmaf(pe, v2.x, a4); a5 = fmaf(pe, v2.y, a5);
        a6 = fmaf(pe, v3.x, a6); a7 = fmaf(pe, v3.y, a7);
    }

    s  += __shfl_xor_sync(0xffffffffu, s,  16);
    a0 += __shfl_xor_sync(0xffffffffu, a0, 16);
    a1 += __shfl_xor_sync(0xffffffffu, a1, 16);
    a2 += __shfl_xor_sync(0xffffffffu, a2, 16);
    a3 += __shfl_xor_sync(0xffffffffu, a3, 16);
    a4 += __shfl_xor_sync(0xffffffffu, a4, 16);
    a5 += __shfl_xor_sync(0xffffffffu, a5, 16);
    a6 += __shfl_xor_sync(0xffffffffu, a6, 16);
    a7 += __shfl_xor_sync(0xffffffffu, a7, 16);

    float r = 1.f / (s + 1e-37f);
    float o0 = fmaxf(a0 * r, 0.f), o1 = fmaxf(a1 * r, 0.f);
    float o2 = fmaxf(a2 * r, 0.f), o3 = fmaxf(a3 * r, 0.f);
    float o4 = fmaxf(a4 * r, 0.f), o5 = fmaxf(a5 * r, 0.f);
    float o6 = fmaxf(a6 * r, 0.f), o7 = fmaxf(a7 * r, 0.f);

    if (LAYER == 0) {
        if (half == 0) {
            __half2 h0 = __floats2half2_rn(o0, o1);
            __half2 h1 = __floats2half2_rn(o2, o3);
            __half2 h2 = __floats2half2_rn(o4, o5);
            __half2 h3 = __floats2half2_rn(o6, o7);
            uint4 u;
            u.x = *reinterpret_cast<unsigned*>(&h0);
            u.y = *reinterpret_cast<unsigned*>(&h1);
            u.z = *reinterpret_cast<unsigned*>(&h2);
            u.w = *reinterpret_cast<unsigned*>(&h3);
            *reinterpret_cast<uint4*>(g_x1h + (size_t)node * 128 + D0) = u;
        }
    } else {
        const float4* wp = reinterpret_cast<const float4*>(wc + D0);
        float4 wa = wp[0], wb = wp[1];
        float p = o0 * wa.x;
        p = fmaf(o1, wa.y, p); p = fmaf(o2, wa.z, p); p = fmaf(o3, wa.w, p);
        p = fmaf(o4, wb.x, p); p = fmaf(o5, wb.y, p);
        p = fmaf(o6, wb.z, p); p = fmaf(o7, wb.w, p);
        p += __shfl_xor_sync(0xffffffffu, p, 1);
        p += __shfl_xor_sync(0xffffffffu, p, 2);
        p += __shfl_xor_sync(0xffffffffu, p, 4);
        p += __shfl_xor_sync(0xffffffffu, p, 8);
        if (lane == 0) g_xc[node] = p;
    }
}

// ---------------- final: out[e] = xc[src] + xc[dst] + bc ; re-zero counters ----------------
__global__ void final_kernel(const int* __restrict__ ei, const float* __restrict__ bc,
                             float* __restrict__ out, int E) {
    int e = blockIdx.x * blockDim.x + threadIdx.x;
    if (e < N_NODES) { g_deg[e] = 0; g_cur[e] = 0; }   // ready for next replay
    if (e >= E) return;
    out[e] = g_xc[ei[e]] + g_xc[ei[E + e]] + bc[0];
}

// ---------------- launch (capture fork/join for overlap; R13 structure) ----------------
extern "C" void kernel_launch(void* const* d_in, const int* in_sizes, int n_in,
                              void* d_out, int out_size) {
    const int*   ei  = (const int*)  d_in[0];
    const float* ea  = (const float*)d_in[1];
    const float* emb = (const float*)d_in[3];
    const float *wq1 = (const float*)d_in[4],  *bq1 = (const float*)d_in[5];
    const float *wk1 = (const float*)d_in[6],  *bk1 = (const float*)d_in[7];
    const float *wv1 = (const float*)d_in[8],  *bv1 = (const float*)d_in[9];
    const float *wt1 = (const float*)d_in[10], *bt1 = (const float*)d_in[11];
    const float *wq2 = (const float*)d_in[12], *bq2 = (const float*)d_in[13];
    const float *wk2 = (const float*)d_in[14], *bk2 = (const float*)d_in[15];
    const float *wv2 = (const float*)d_in[16], *bv2 = (const float*)d_in[17];
    const float *wt2 = (const float*)d_in[18], *bt2 = (const float*)d_in[19];
    const float *wc  = (const float*)d_in[20], *bc  = (const float*)d_in[21];
    float* out = (float*)d_out;

    int E = in_sizes[0] / 2;

    // Fresh side stream + events each call (deterministic; host-side objects,
    // intentionally leaked — kernel_launch runs only a handful of times).
    cudaStream_t s2;
    cudaStreamCreateWithFlags(&s2, cudaStreamNonBlocking);
    cudaEvent_t ev1, ev2;
    cudaEventCreateWithFlags(&ev1, cudaEventDisableTiming);
    cudaEventCreateWithFlags(&ev2, cudaEventDisableTiming);

    // setup: conversions + histogram (g_deg zeroed by previous call's final_kernel)
    setup_kernel<<<(N_NODES * 64 + 255) / 256, 256>>>(emb, wq1, wk1, wv1, wt1,
                                                      wq2, wk2, wv2, wt2, ei, E);
    cudaEventRecord(ev1, 0);
    cudaStreamWaitEvent(s2, ev1, 0);

    // fork: sort chain on s2, node_linear<0> on main (independent)
    scanA_kernel<<<SCAN_BLOCKS, 256, 0, s2>>>(N_NODES);
    scanB_kernel<<<1, 256, 0, s2>>>(SCAN_BLOCKS, N_NODES);
    scanC_kernel<<<SCAN_BLOCKS, 256, 0, s2>>>(N_NODES);
    scatter_kernel<<<(E + 255) / 256, 256, 0, s2>>>(ei, ea, E);
    cudaEventRecord(ev2, s2);

    node_linear_wmma<0><<<N_PAD / 32, 256>>>(bq1, bk1, bv1, bt1);

    // join: edge_agg<0> needs both scatter and node_linear<0>
    cudaStreamWaitEvent(0, ev2, 0);
    edge_agg_kernel<0><<<(N_NODES + 3) / 4, 128>>>(wc);

    node_linear_wmma<1><<<N_PAD / 32, 256>>>(bq2, bk2, bv2, bt2);
    edge_agg_kernel<1><<<(N_NODES + 3) / 4, 128>>>(wc);

    final_kernel<<<(E + 255) / 256, 256>>>(ei, bc, out, E);
}